// round 13
// baseline (speedup 1.0000x reference)
#include <cuda_runtime.h>

typedef unsigned long long u64;
typedef unsigned int u32;

#define T_STEPS 2048
#define NB 8
#define NH 16
#define BH (NB*NH)
#define KF 32
#define VF 64
#define KS 128
#define VS 64

// ---- packed f32x2 helpers ----
__device__ __forceinline__ u64 pack2(float lo, float hi) {
    u64 r;
    asm("mov.b64 %0, {%1, %2};" : "=l"(r) : "r"(__float_as_uint(lo)), "r"(__float_as_uint(hi)));
    return r;
}
__device__ __forceinline__ void unpack2(u64 a, float& lo, float& hi) {
    u32 l, h;
    asm("mov.b64 {%0, %1}, %2;" : "=r"(l), "=r"(h) : "l"(a));
    lo = __uint_as_float(l); hi = __uint_as_float(h);
}
__device__ __forceinline__ u64 fma2_(u64 a, u64 b, u64 c) {
    u64 d; asm("fma.rn.f32x2 %0, %1, %2, %3;" : "=l"(d) : "l"(a), "l"(b), "l"(c)); return d;
}
__device__ __forceinline__ u64 mul2_(u64 a, u64 b) {
    u64 d; asm("mul.rn.f32x2 %0, %1, %2;" : "=l"(d) : "l"(a), "l"(b)); return d;
}
__device__ __forceinline__ u64 add2_(u64 a, u64 b) {
    u64 d; asm("add.rn.f32x2 %0, %1, %2;" : "=l"(d) : "l"(a), "l"(b)); return d;
}
__device__ __forceinline__ u64 shfl_xor_u64(u64 v, int m) {
    u32 lo, hi;
    asm("mov.b64 {%0, %1}, %2;" : "=r"(lo), "=r"(hi) : "l"(v));
    lo = __shfl_xor_sync(0xffffffffu, lo, m);
    hi = __shfl_xor_sync(0xffffffffu, hi, m);
    u64 r;
    asm("mov.b64 %0, {%1, %2};" : "=l"(r) : "r"(lo), "r"(hi));
    return r;
}

// ---- mbarrier helpers ----
__device__ __forceinline__ void mbar_init(u32 addr, u32 count) {
    asm volatile("mbarrier.init.shared.b64 [%0], %1;" :: "r"(addr), "r"(count) : "memory");
}
__device__ __forceinline__ void mbar_arrive(u32 addr) {
    asm volatile("mbarrier.arrive.release.cta.shared::cta.b64 _, [%0];" :: "r"(addr) : "memory");
}
__device__ __forceinline__ void mbar_wait(u32 addr, u32 parity) {
    asm volatile(
        "{\n\t.reg .pred P;\n\t"
        "WL%=:\n\t"
        "mbarrier.try_wait.parity.acquire.cta.shared::cta.b64 P, [%0], %1, 0x989680;\n\t"
        "@P bra WD%=;\n\t"
        "bra WL%=;\n\t"
        "WD%=:\n\t}"
        :: "r"(addr), "r"(parity) : "memory");
}
__device__ __forceinline__ void cp16(u32 dst, const void* s) {
    asm volatile("cp.async.cg.shared.global [%0], [%1], 16;" :: "r"(dst), "l"(s));
}
__device__ __forceinline__ void cp4(u32 dst, const void* s) {
    asm volatile("cp.async.ca.shared.global [%0], [%1], 4;" :: "r"(dst), "l"(s));
}

// smem per-step stage (floats) — natural order, no swizzle:
// [0,32) kf | [32,64) qf | [64,192) ks | [192,320) qs
// [320,384) vf | [384,448) vs | [448,453) scalars {df,ds,g,mf,ms} | pad 456
#define STEP_F 456
#define MEGA   8                 // steps per mega-stage
#define NMEGA  3                 // ring = 24 steps = 43.8 KB static smem
#define NMEGAI (T_STEPS/MEGA)    // 256 mega-iterations

#define NCWARP 16                // consumer warps (4 output columns each)
#define NTHREADS (NCWARP*32 + 32)

// per-step register staging (double-buffered software pipeline)
struct SR {
    float4 sc4;            // df, ds, g, mf
    float  msv;            // ms
    float  kf, qf;         // fast k/q, row = lane
    float4 ks4, qs4;       // slow k/q, rows 4l..4l+3
    ulonglong2 vfP, vsP;   // v_fast / v_slow cols 4w..4w+3 packed in pairs
};

__device__ __forceinline__ void loadregs(SR& r, const float* cur, int l, int w) {
    r.sc4 = *(const float4*)(cur + 448);
    r.msv = cur[452];
    r.kf  = cur[l];
    r.qf  = cur[32 + l];
    r.ks4 = *(const float4*)(cur + 64  + 4*l);
    r.qs4 = *(const float4*)(cur + 192 + 4*l);
    r.vfP = *(const ulonglong2*)(cur + 320 + 4*w);
    r.vsP = *(const ulonglong2*)(cur + 384 + 4*w);
}

__global__ __launch_bounds__(NTHREADS, 1)
void e90_kernel(const float* __restrict__ k_fast, const float* __restrict__ v_fast,
                const float* __restrict__ q_fast, const float* __restrict__ decay_fast,
                const float* __restrict__ k_slow, const float* __restrict__ v_slow,
                const float* __restrict__ q_slow, const float* __restrict__ decay_slow,
                const float* __restrict__ slow_gate, const float* __restrict__ mix_fast,
                const float* __restrict__ mix_slow, const float* __restrict__ S_fast0,
                const float* __restrict__ S_slow0, float* __restrict__ out)
{
    __shared__ __align__(16) float ring[NMEGA * MEGA * STEP_F];
    __shared__ __align__(8)  u64  mbar[2 * NMEGA];   // [0..2] full, [3..5] empty

    const int tid = threadIdx.x;
    const int bh  = blockIdx.x;

    const u32 sb = (u32)__cvta_generic_to_shared(ring);
    const u32 bb = (u32)__cvta_generic_to_shared(mbar);

    if (tid == 0) {
        #pragma unroll
        for (int i = 0; i < NMEGA; i++) {
            mbar_init(bb + i*8, 32);                 // full: 32 producer-lane arrives
            mbar_init(bb + (NMEGA + i)*8, NCWARP);   // empty: 16 consumer-warp arrives
        }
    }
    __syncthreads();   // the ONLY block barrier

    if (tid >= NCWARP*32) {
        // ================= PRODUCER WARP =================
        const int lane = tid - NCWARP*32;
        const float* src[4];
        int off[4], strd[4], wid[4];
        #pragma unroll
        for (int r = 0; r < 4; r++) {
            int c = r*32 + lane;
            src[r] = 0; off[r] = -1; strd[r] = 0; wid[r] = 1;
            if (c < 8)        {               src[r] = k_fast + (size_t)bh*KF + c*4;  off[r] = c*4;           strd[r] = BH*KF; }
            else if (c < 16)  { int g = c-8;  src[r] = q_fast + (size_t)bh*KF + g*4;  off[r] = 32  + g*4;     strd[r] = BH*KF; }
            else if (c < 48)  { int g = c-16; src[r] = k_slow + (size_t)bh*KS + g*4;  off[r] = 64  + g*4;     strd[r] = BH*KS; }
            else if (c < 80)  { int g = c-48; src[r] = q_slow + (size_t)bh*KS + g*4;  off[r] = 192 + g*4;     strd[r] = BH*KS; }
            else if (c < 96)  { int g = c-80; src[r] = v_fast + (size_t)bh*VF + g*4;  off[r] = 320 + g*4;     strd[r] = BH*VF; }
            else if (c < 112) { int g = c-96; src[r] = v_slow + (size_t)bh*VS + g*4;  off[r] = 384 + g*4;     strd[r] = BH*VS; }
            else if (c < 117) {
                const float* a5[5] = {decay_fast, decay_slow, slow_gate, mix_fast, mix_slow};
                src[r] = a5[c-112] + bh; off[r] = 448 + (c-112); strd[r] = BH; wid[r] = 0;
            }
        }

        int sm = 0; u32 eph = 1;   // fresh empty barriers pass parity-1 wait immediately
        for (int m = 0; m < NMEGAI; m++) {
            mbar_wait(bb + (NMEGA + sm)*8, eph);     // wait stage free
            u32 stg = sb + (u32)(sm * MEGA * STEP_F) * 4u;
            #pragma unroll
            for (int s = 0; s < MEGA; s++) {
                u32 stp = stg + (u32)(s * STEP_F) * 4u;
                #pragma unroll
                for (int r = 0; r < 4; r++) {
                    if (off[r] >= 0) {
                        u32 dst = stp + (u32)off[r] * 4u;
                        if (wid[r]) cp16(dst, src[r]); else cp4(dst, src[r]);
                        src[r] += strd[r];
                    }
                }
            }
            asm volatile("cp.async.mbarrier.arrive.noinc.shared.b64 [%0];" :: "r"(bb + sm*8) : "memory");
            if (sm == NMEGA-1) { sm = 0; eph ^= 1; } else sm++;
        }
    } else {
        // ================= 16 CONSUMER WARPS =================
        // warp w owns output columns 4w..4w+3; lane l owns fast row l + slow rows 4l..4l+3
        const int w = tid >> 5;
        const int l = tid & 31;

        // states packed along COLUMNS: Sf[j] = (col 4w+2j, 4w+2j+1) of fast row l
        u64 Sf[2], Ss[4][2];
        {
            const float* p0 = S_fast0 + (size_t)bh*KF*VF + (size_t)l*VF + 4*w;
            float4 a = *(const float4*)p0;
            Sf[0] = pack2(a.x, a.y); Sf[1] = pack2(a.z, a.w);
            #pragma unroll
            for (int p = 0; p < 4; p++) {
                const float* p1 = S_slow0 + (size_t)bh*KS*VS + (size_t)(4*l + p)*VS + 4*w;
                float4 c = *(const float4*)p1;
                Ss[p][0] = pack2(c.x, c.y); Ss[p][1] = pack2(c.z, c.w);
            }
        }

        float* outO = out + (size_t)BH*(KF*VF + KS*VS) + (size_t)bh*VF + 4*w;
        const bool elect   = (l == 0);
        const bool writer  = ((l & 7) == 0);     // lanes 0,8,16,24 each write one column
        const int  wcol    = l >> 3;             // column (within the warp's 4) this lane writes
        const bool hi16    = (l & 16) != 0;
        const bool hi8     = (l & 8)  != 0;

        auto compute = [&](const SR& r) {
            float df = r.sc4.x, ds = r.sc4.y, g = r.sc4.z, mf = r.sc4.w;
            float ms = r.msv;
            float de = 1.0f + g * (ds - 1.0f);      // g*ds + (1-g)

            u64 df2 = pack2(df, df);
            u64 de2 = pack2(de, de);
            u64 g2  = pack2(g, g);

            u64 vf2[2] = { r.vfP.x, r.vfP.y };
            u64 vs2[2] = { mul2_(g2, r.vsP.x), mul2_(g2, r.vsP.y) };

            // fast state: row l, 2 col-pairs
            u64 kf2 = pack2(r.kf, r.kf);
            u64 qf2 = pack2(r.qf, r.qf);
            u64 accf[2];
            #pragma unroll
            for (int j = 0; j < 2; j++) {
                Sf[j]   = fma2_(df2, Sf[j], mul2_(kf2, vf2[j]));
                accf[j] = mul2_(qf2, Sf[j]);
            }

            // slow state: rows 4l..4l+3, 2 col-pairs
            const float ksv[4] = { r.ks4.x, r.ks4.y, r.ks4.z, r.ks4.w };
            const float qsv[4] = { r.qs4.x, r.qs4.y, r.qs4.z, r.qs4.w };
            u64 accs[2];
            {
                u64 k2 = pack2(ksv[0], ksv[0]);
                u64 q2 = pack2(qsv[0], qsv[0]);
                #pragma unroll
                for (int j = 0; j < 2; j++) {
                    Ss[0][j] = fma2_(de2, Ss[0][j], mul2_(k2, vs2[j]));
                    accs[j]  = mul2_(q2, Ss[0][j]);
                }
            }
            #pragma unroll
            for (int p = 1; p < 4; p++) {
                u64 k2 = pack2(ksv[p], ksv[p]);
                u64 q2 = pack2(qsv[p], qsv[p]);
                #pragma unroll
                for (int j = 0; j < 2; j++) {
                    Ss[p][j] = fma2_(de2, Ss[p][j], mul2_(k2, vs2[j]));
                    accs[j]  = fma2_(q2, Ss[p][j], accs[j]);
                }
            }

            // mix -> a0 = cols(4w,4w+1), a1 = cols(4w+2,4w+3)
            u64 mf2 = pack2(mf, mf), ms2 = pack2(ms, ms);
            u64 a0 = fma2_(ms2, accs[0], mul2_(mf2, accf[0]));
            u64 a1 = fma2_(ms2, accs[1], mul2_(mf2, accf[1]));

            // ---- value-halving butterfly over 32 lanes (6 SHFL) ----
            // xor16: low lanes keep cols01, high keep cols23
            u64 kA = hi16 ? a1 : a0;
            u64 sA = hi16 ? a0 : a1;
            kA = add2_(kA, shfl_xor_u64(sA, 16));
            // xor8: keep one column
            float x, y;
            unpack2(kA, x, y);
            float sD = hi8 ? x : y;
            float kD = hi8 ? y : x;
            kD += __shfl_xor_sync(0xffffffffu, sD, 8);
            // xor4/2/1: reduce the single remaining value over the 8-lane group
            kD += __shfl_xor_sync(0xffffffffu, kD, 4);
            kD += __shfl_xor_sync(0xffffffffu, kD, 2);
            kD += __shfl_xor_sync(0xffffffffu, kD, 1);
            // lane group 8c..8c+7 holds full sum of column (4w + c)
            if (writer) outO[wcol] = kD;
            outO += (size_t)BH * VF;
        };

        SR R[2];
        int sm = 0; u32 cph = 0;
        mbar_wait(bb + 0, 0);
        loadregs(R[0], ring, l, w);

        for (int m = 0; m < NMEGAI; m++) {
            const float* base = ring + sm * MEGA * STEP_F;
            const int nsm = (sm == NMEGA-1) ? 0 : sm+1;
            const u32 nc  = (sm == NMEGA-1) ? (cph ^ 1) : cph;
            #pragma unroll
            for (int s = 0; s < MEGA; s++) {
                if (s < MEGA-1) {
                    loadregs(R[(s+1)&1], base + (s+1)*STEP_F, l, w);
                } else if (m < NMEGAI-1) {
                    // cross-boundary preload hidden under the final compute of this stage
                    mbar_wait(bb + nsm*8, nc);
                    loadregs(R[0], ring + nsm * MEGA * STEP_F, l, w);
                }
                compute(R[s&1]);
            }
            if (elect) mbar_arrive(bb + (NMEGA + sm)*8);   // stage consumed (all reads done)
            sm = nsm; cph = nc;
        }

        // final states
        {
            float* oSf = out + (size_t)bh*KF*VF + (size_t)l*VF + 4*w;
            float a0,a1,a2,a3;
            unpack2(Sf[0], a0, a1); unpack2(Sf[1], a2, a3);
            *(float4*)oSf = make_float4(a0, a1, a2, a3);

            #pragma unroll
            for (int p = 0; p < 4; p++) {
                float* oSs = out + (size_t)BH*KF*VF + (size_t)bh*KS*VS + (size_t)(4*l + p)*VS + 4*w;
                float c0,c1,c2,c3;
                unpack2(Ss[p][0], c0, c1); unpack2(Ss[p][1], c2, c3);
                *(float4*)oSs = make_float4(c0, c1, c2, c3);
            }
        }
    }
}

extern "C" void kernel_launch(void* const* d_in, const int* in_sizes, int n_in,
                              void* d_out, int out_size) {
    (void)in_sizes; (void)n_in; (void)out_size;
    e90_kernel<<<BH, NTHREADS>>>(
        (const float*)d_in[0],  (const float*)d_in[1],  (const float*)d_in[2],
        (const float*)d_in[3],  (const float*)d_in[4],  (const float*)d_in[5],
        (const float*)d_in[6],  (const float*)d_in[7],  (const float*)d_in[8],
        (const float*)d_in[9],  (const float*)d_in[10], (const float*)d_in[11],
        (const float*)d_in[12], (float*)d_out);
}